// round 1
// baseline (speedup 1.0000x reference)
#include <cuda_runtime.h>
#include <math.h>

#define TT 2048
#define CC 2048
#define HH 16
#define DN 128
#define DR 64
#define DV 128
#define QKD 192
#define RQ 1536
#define RKV 512
#define EPSF 1e-6f
#define SCALEF 0.07216878364870323f  // 192^-0.5

// ---------------- scratch (device globals; no allocation allowed) ----------------
__device__ float g_qlat[TT * RQ];          // 12.6 MB
__device__ float g_q[TT * HH * QKD];       // 25.2 MB  [T, H, 192]
__device__ float g_kvpe[TT * (RKV + DR)];  // 4.7 MB   [T, 576]
__device__ float g_kvlat[TT * RKV];        // 4.2 MB
__device__ float g_kvb[TT * HH * (DN + DV)]; // 33.5 MB [T, H, 256]
__device__ float g_y[TT * CC];             // 16.8 MB

// ---------------- SGEMM: C[M,N] = A[M,K] @ B[N,K]^T + bias[N] ----------------
// 128x128 block, BK=8, 256 threads, 8x8 microtile, float4 global loads.
__global__ void __launch_bounds__(256) sgemm_bias(
    const float* __restrict__ A, const float* __restrict__ B,
    const float* __restrict__ bias, float* __restrict__ Cm,
    int M, int N, int K)
{
    __shared__ float As[8][128];
    __shared__ float Bs[8][128];

    int tid = threadIdx.x;
    int tx = tid & 15, ty = tid >> 4;
    int m0 = blockIdx.y * 128, n0 = blockIdx.x * 128;

    int lrow = tid >> 1;             // 0..127
    int lcol = (tid & 1) * 4;        // 0 or 4

    const float* Aptr = A + (size_t)(m0 + lrow) * K + lcol;
    bool bvalid = (n0 + lrow) < N;
    const float* Bptr = B + (size_t)(bvalid ? (n0 + lrow) : 0) * K + lcol;

    float acc[8][8];
#pragma unroll
    for (int i = 0; i < 8; i++)
#pragma unroll
        for (int j = 0; j < 8; j++) acc[i][j] = 0.f;

    for (int k0 = 0; k0 < K; k0 += 8) {
        float4 av = *(const float4*)(Aptr + k0);
        float4 bv = bvalid ? *(const float4*)(Bptr + k0) : make_float4(0.f, 0.f, 0.f, 0.f);
        As[lcol + 0][lrow] = av.x; As[lcol + 1][lrow] = av.y;
        As[lcol + 2][lrow] = av.z; As[lcol + 3][lrow] = av.w;
        Bs[lcol + 0][lrow] = bv.x; Bs[lcol + 1][lrow] = bv.y;
        Bs[lcol + 2][lrow] = bv.z; Bs[lcol + 3][lrow] = bv.w;
        __syncthreads();
#pragma unroll
        for (int kk = 0; kk < 8; kk++) {
            float4 a0 = *(const float4*)&As[kk][ty * 8];
            float4 a1 = *(const float4*)&As[kk][ty * 8 + 4];
            float4 b0 = *(const float4*)&Bs[kk][tx * 8];
            float4 b1 = *(const float4*)&Bs[kk][tx * 8 + 4];
            float a[8] = {a0.x, a0.y, a0.z, a0.w, a1.x, a1.y, a1.z, a1.w};
            float b[8] = {b0.x, b0.y, b0.z, b0.w, b1.x, b1.y, b1.z, b1.w};
#pragma unroll
            for (int i = 0; i < 8; i++)
#pragma unroll
                for (int j = 0; j < 8; j++) acc[i][j] += a[i] * b[j];
        }
        __syncthreads();
    }

#pragma unroll
    for (int i = 0; i < 8; i++) {
        int m = m0 + ty * 8 + i;
#pragma unroll
        for (int j = 0; j < 8; j++) {
            int n = n0 + tx * 8 + j;
            if (n < N) Cm[(size_t)m * N + n] = acc[i][j] + bias[n];
        }
    }
}

// ---------------- RMSNorm (row-wise) ----------------
__global__ void __launch_bounds__(256) rmsnorm_kernel(
    const float* __restrict__ src, int srcStride,
    float* __restrict__ dst, int dstStride,
    const float* __restrict__ w, int cols)
{
    int row = blockIdx.x;
    const float* s = src + (size_t)row * srcStride;
    float* d = dst + (size_t)row * dstStride;
    float sum = 0.f;
    for (int i = threadIdx.x; i < cols; i += 256) { float v = s[i]; sum += v * v; }
    __shared__ float red[256];
    red[threadIdx.x] = sum;
    __syncthreads();
    for (int o = 128; o > 0; o >>= 1) {
        if (threadIdx.x < o) red[threadIdx.x] += red[threadIdx.x + o];
        __syncthreads();
    }
    float inv = rsqrtf(red[0] / (float)cols + EPSF);
    for (int i = threadIdx.x; i < cols; i += 256) d[i] = s[i] * inv * w[i];
}

// ---------------- RoPE ----------------
__global__ void rope_q_kernel(const float* __restrict__ freqs) {
    int idx = blockIdx.x * blockDim.x + threadIdx.x;
    if (idx >= TT * HH * 32) return;
    int i = idx & 31;
    int h = (idx >> 5) & 15;
    int t = idx >> 9;
    float f = freqs[t * 32 + i];
    float c = cosf(f), s = sinf(f);
    float* p = g_q + (size_t)t * (HH * QKD) + h * QKD + DN + 2 * i;
    float x0 = p[0], x1 = p[1];
    p[0] = x0 * c - x1 * s;
    p[1] = x0 * s + x1 * c;
}

__global__ void rope_k_kernel(const float* __restrict__ freqs) {
    int idx = blockIdx.x * blockDim.x + threadIdx.x;
    if (idx >= TT * 32) return;
    int i = idx & 31;
    int t = idx >> 5;
    float f = freqs[t * 32 + i];
    float c = cosf(f), s = sinf(f);
    float* p = g_kvpe + (size_t)t * (RKV + DR) + RKV + 2 * i;
    float x0 = p[0], x1 = p[1];
    p[0] = x0 * c - x1 * s;
    p[1] = x0 * s + x1 * c;
}

// ---------------- Flash attention (causal, online softmax) ----------------
// Block = one (head, 64-row q tile). 256 threads: 16x16 grid, 4x4 score microtile,
// 4x8 output microtile. Shared pitches padded to dodge bank conflicts.
#define QP 193
#define VP 132
#define PP 65
#define ATTN_SMEM ((64 * QP * 2 + 64 * VP + 64 * PP + 3 * 64) * 4)

__global__ void __launch_bounds__(256) attn_kernel(
    const float* __restrict__ q, const float* __restrict__ kvb,
    const float* __restrict__ kvpe, float* __restrict__ y)
{
    extern __shared__ float sm[];
    float* Qs = sm;                  // 64 x 193
    float* Ks = Qs + 64 * QP;        // 64 x 193
    float* Vs = Ks + 64 * QP;        // 64 x 132
    float* Ps = Vs + 64 * VP;        // 64 x 65
    float* m_s  = Ps + 64 * PP;
    float* l_s  = m_s + 64;
    float* al_s = l_s + 64;

    int h = blockIdx.y;
    int qt = gridDim.x - 1 - blockIdx.x;   // heavy tiles first
    int tid = threadIdx.x;
    int tx = tid & 15, ty = tid >> 4;

    for (int i = tid; i < 64 * QKD; i += 256) {
        int r = i / QKD, d = i - r * QKD;
        Qs[r * QP + d] = q[(size_t)(qt * 64 + r) * (HH * QKD) + h * QKD + d] * SCALEF;
    }
    if (tid < 64) { m_s[tid] = -1e30f; l_s[tid] = 0.f; }

    float o[4][8];
#pragma unroll
    for (int i = 0; i < 4; i++)
#pragma unroll
        for (int c = 0; c < 8; c++) o[i][c] = 0.f;

    for (int kt = 0; kt <= qt; kt++) {
        __syncthreads();   // prior tile consumers done before overwrite
        for (int i = tid; i < 64 * QKD; i += 256) {
            int r = i / QKD, d = i - r * QKD;
            int tk = kt * 64 + r;
            Ks[r * QP + d] = (d < DN)
                ? kvb[(size_t)tk * (HH * 256) + h * 256 + d]
                : kvpe[(size_t)tk * (RKV + DR) + RKV + (d - DN)];
        }
        for (int i = tid; i < 64 * DV; i += 256) {
            int r = i >> 7, c = i & 127;
            Vs[r * VP + c] = kvb[(size_t)(kt * 64 + r) * (HH * 256) + h * 256 + DN + c];
        }
        __syncthreads();

        float s4[4][4];
#pragma unroll
        for (int i = 0; i < 4; i++)
#pragma unroll
            for (int j = 0; j < 4; j++) s4[i][j] = 0.f;

        const float* qp = Qs + (ty * 4) * QP;
        const float* kp = Ks + (tx * 4) * QP;
#pragma unroll 4
        for (int d = 0; d < QKD; d++) {
            float a0 = qp[d], a1 = qp[d + QP], a2 = qp[d + 2 * QP], a3 = qp[d + 3 * QP];
            float b0 = kp[d], b1 = kp[d + QP], b2 = kp[d + 2 * QP], b3 = kp[d + 3 * QP];
            s4[0][0] += a0 * b0; s4[0][1] += a0 * b1; s4[0][2] += a0 * b2; s4[0][3] += a0 * b3;
            s4[1][0] += a1 * b0; s4[1][1] += a1 * b1; s4[1][2] += a1 * b2; s4[1][3] += a1 * b3;
            s4[2][0] += a2 * b0; s4[2][1] += a2 * b1; s4[2][2] += a2 * b2; s4[2][3] += a2 * b3;
            s4[3][0] += a3 * b0; s4[3][1] += a3 * b1; s4[3][2] += a3 * b2; s4[3][3] += a3 * b3;
        }

        if (kt == qt) {
#pragma unroll
            for (int i = 0; i < 4; i++)
#pragma unroll
                for (int j = 0; j < 4; j++)
                    if (tx * 4 + j > ty * 4 + i) s4[i][j] = -1e30f;
        }

#pragma unroll
        for (int i = 0; i < 4; i++) {
            int row = ty * 4 + i;
            float mx = fmaxf(fmaxf(s4[i][0], s4[i][1]), fmaxf(s4[i][2], s4[i][3]));
#pragma unroll
            for (int off = 8; off >= 1; off >>= 1)
                mx = fmaxf(mx, __shfl_xor_sync(0xffffffffu, mx, off));
            float mo = m_s[row];
            float mn = fmaxf(mo, mx);
            float sum = 0.f;
#pragma unroll
            for (int j = 0; j < 4; j++) {
                float p = __expf(s4[i][j] - mn);
                s4[i][j] = p;
                sum += p;
            }
#pragma unroll
            for (int off = 8; off >= 1; off >>= 1)
                sum += __shfl_xor_sync(0xffffffffu, sum, off);
            if (tx == 0) {
                float al = __expf(mo - mn);
                al_s[row] = al;
                l_s[row] = l_s[row] * al + sum;
                m_s[row] = mn;
            }
            Ps[row * PP + tx * 4 + 0] = s4[i][0];
            Ps[row * PP + tx * 4 + 1] = s4[i][1];
            Ps[row * PP + tx * 4 + 2] = s4[i][2];
            Ps[row * PP + tx * 4 + 3] = s4[i][3];
        }
        __syncthreads();

        float al[4];
#pragma unroll
        for (int i = 0; i < 4; i++) {
            al[i] = al_s[ty * 4 + i];
#pragma unroll
            for (int c = 0; c < 8; c++) o[i][c] *= al[i];
        }
#pragma unroll 2
        for (int j = 0; j < 64; j++) {
            float4 v0 = *(const float4*)&Vs[j * VP + tx * 8];
            float4 v1 = *(const float4*)&Vs[j * VP + tx * 8 + 4];
            float vv[8] = {v0.x, v0.y, v0.z, v0.w, v1.x, v1.y, v1.z, v1.w};
#pragma unroll
            for (int i = 0; i < 4; i++) {
                float p = Ps[(ty * 4 + i) * PP + j];
#pragma unroll
                for (int c = 0; c < 8; c++) o[i][c] += p * vv[c];
            }
        }
    }

#pragma unroll
    for (int i = 0; i < 4; i++) {
        int row = ty * 4 + i;
        float inv = 1.f / l_s[row];
        int t = qt * 64 + row;
#pragma unroll
        for (int c = 0; c < 8; c++)
            y[(size_t)t * CC + h * DV + tx * 8 + c] = o[i][c] * inv;
    }
}

// ---------------- launch ----------------
extern "C" void kernel_launch(void* const* d_in, const int* in_sizes, int n_in,
                              void* d_out, int out_size) {
    const float* x        = (const float*)d_in[0];
    const float* freqs    = (const float*)d_in[1];
    const float* wq_a     = (const float*)d_in[2];
    const float* bq_a     = (const float*)d_in[3];
    const float* q_norm_w = (const float*)d_in[4];
    const float* wq_b     = (const float*)d_in[5];
    const float* bq_b     = (const float*)d_in[6];
    const float* wkv_a    = (const float*)d_in[7];
    const float* bkv_a    = (const float*)d_in[8];
    const float* kv_norm_w= (const float*)d_in[9];
    const float* wkv_b    = (const float*)d_in[10];
    const float* bkv_b    = (const float*)d_in[11];
    const float* wo       = (const float*)d_in[12];
    const float* bo       = (const float*)d_in[13];
    float* out = (float*)d_out;

    float *qlat, *qbuf, *kvpe, *kvlat, *kvb, *ybuf;
    cudaGetSymbolAddress((void**)&qlat,  g_qlat);
    cudaGetSymbolAddress((void**)&qbuf,  g_q);
    cudaGetSymbolAddress((void**)&kvpe,  g_kvpe);
    cudaGetSymbolAddress((void**)&kvlat, g_kvlat);
    cudaGetSymbolAddress((void**)&kvb,   g_kvb);
    cudaGetSymbolAddress((void**)&ybuf,  g_y);

    cudaFuncSetAttribute(attn_kernel, cudaFuncAttributeMaxDynamicSharedMemorySize, ATTN_SMEM);

    // Q path
    sgemm_bias<<<dim3(RQ / 128, TT / 128), 256>>>(x, wq_a, bq_a, qlat, TT, RQ, CC);
    rmsnorm_kernel<<<TT, 256>>>(qlat, RQ, qlat, RQ, q_norm_w, RQ);
    sgemm_bias<<<dim3((HH * QKD) / 128, TT / 128), 256>>>(qlat, wq_b, bq_b, qbuf, TT, HH * QKD, RQ);
    rope_q_kernel<<<(TT * HH * 32 + 255) / 256, 256>>>(freqs);

    // KV path
    sgemm_bias<<<dim3((RKV + DR + 127) / 128, TT / 128), 256>>>(x, wkv_a, bkv_a, kvpe, TT, RKV + DR, CC);
    rope_k_kernel<<<(TT * 32 + 255) / 256, 256>>>(freqs);
    rmsnorm_kernel<<<TT, 256>>>(kvpe, RKV + DR, kvlat, RKV, kv_norm_w, RKV);
    sgemm_bias<<<dim3((HH * 256) / 128, TT / 128), 256>>>(kvlat, wkv_b, bkv_b, kvb, TT, HH * 256, RKV);

    // Attention
    attn_kernel<<<dim3(TT / 64, HH), 256, ATTN_SMEM>>>(qbuf, kvb, kvpe, ybuf);

    // Output projection
    sgemm_bias<<<dim3(CC / 128, TT / 128), 256>>>(ybuf, wo, bo, out, TT, CC, CC);
}

// round 2
// speedup vs baseline: 3.2401x; 3.2401x over previous
#include <cuda_runtime.h>
#include <math.h>

#define TT 2048
#define CC 2048
#define HH 16
#define DN 128
#define DR 64
#define DV 128
#define QKD 192
#define RQ 1536
#define RKV 512
#define EPSF 1e-6f
#define SCALEF 0.07216878364870323f  // 192^-0.5

// ---------------- scratch (device globals; no allocation allowed) ----------------
__device__ float g_qlat[TT * RQ];
__device__ float g_q[TT * HH * QKD];
__device__ float g_kvpe[TT * (RKV + DR)];
__device__ float g_kvlat[TT * RKV];
__device__ float g_kvb[TT * HH * (DN + DV)];
__device__ float g_y[TT * CC];

// ---------------- helpers ----------------
__device__ __forceinline__ float tf32r(float f) {
    unsigned u;
    asm("cvt.rna.tf32.f32 %0, %1;" : "=r"(u) : "f"(f));
    return __uint_as_float(u);
}
__device__ __forceinline__ unsigned fbits(float f) { return __float_as_uint(f); }

__device__ __forceinline__ void mma_tf32(float c[4], const unsigned a[4], const unsigned b[2]) {
    asm volatile(
        "mma.sync.aligned.m16n8k8.row.col.f32.tf32.tf32.f32 "
        "{%0,%1,%2,%3}, {%4,%5,%6,%7}, {%8,%9}, {%0,%1,%2,%3};"
        : "+f"(c[0]), "+f"(c[1]), "+f"(c[2]), "+f"(c[3])
        : "r"(a[0]), "r"(a[1]), "r"(a[2]), "r"(a[3]), "r"(b[0]), "r"(b[1]));
}

// ---------------- tensor-core GEMM: C[M,N] = A[M,K] @ B[N,K]^T + bias ----------------
// 128x128x16 tile, 256 threads (8 warps, 2x4), warp tile 64x32, double-buffered smem.
#define GP 20  // smem pitch (conflict-free fragment loads, float4-alignable)

__global__ void __launch_bounds__(256, 2) gemm_tc(
    const float* __restrict__ A, const float* __restrict__ B,
    const float* __restrict__ bias, float* __restrict__ Cm,
    int M, int N, int K)
{
    __shared__ float As[2][128 * GP];
    __shared__ float Bs[2][128 * GP];

    int tid = threadIdx.x;
    int lane = tid & 31, warp = tid >> 5;
    int wm = warp >> 2, wn = warp & 3;            // 2 x 4 warp grid
    int m0 = blockIdx.y * 128, n0 = blockIdx.x * 128;

    int lr = tid >> 2;          // 0..63
    int lc = (tid & 3) * 4;     // 0,4,8,12

    const float* Ap0 = A + (size_t)(m0 + lr) * K + lc;
    const float* Ap1 = Ap0 + (size_t)64 * K;
    int nr0 = n0 + lr, nr1 = n0 + lr + 64;
    bool bv0 = nr0 < N, bv1 = nr1 < N;
    const float* Bp0 = B + (size_t)(bv0 ? nr0 : 0) * K + lc;
    const float* Bp1 = B + (size_t)(bv1 ? nr1 : 0) * K + lc;

    float acc[4][4][4];
#pragma unroll
    for (int i = 0; i < 4; i++)
#pragma unroll
        for (int j = 0; j < 4; j++)
#pragma unroll
            for (int k = 0; k < 4; k++) acc[i][j][k] = 0.f;

    float4 fa0 = *(const float4*)(Ap0);
    float4 fa1 = *(const float4*)(Ap1);
    float4 fb0 = bv0 ? *(const float4*)(Bp0) : make_float4(0.f, 0.f, 0.f, 0.f);
    float4 fb1 = bv1 ? *(const float4*)(Bp1) : make_float4(0.f, 0.f, 0.f, 0.f);

    *(float4*)&As[0][lr * GP + lc] = make_float4(tf32r(fa0.x), tf32r(fa0.y), tf32r(fa0.z), tf32r(fa0.w));
    *(float4*)&As[0][(lr + 64) * GP + lc] = make_float4(tf32r(fa1.x), tf32r(fa1.y), tf32r(fa1.z), tf32r(fa1.w));
    *(float4*)&Bs[0][lr * GP + lc] = make_float4(tf32r(fb0.x), tf32r(fb0.y), tf32r(fb0.z), tf32r(fb0.w));
    *(float4*)&Bs[0][(lr + 64) * GP + lc] = make_float4(tf32r(fb1.x), tf32r(fb1.y), tf32r(fb1.z), tf32r(fb1.w));
    __syncthreads();

    int cur = 0;
    for (int k0 = 0; k0 < K; k0 += 16) {
        bool more = (k0 + 16) < K;
        if (more) {
            fa0 = *(const float4*)(Ap0 + k0 + 16);
            fa1 = *(const float4*)(Ap1 + k0 + 16);
            fb0 = bv0 ? *(const float4*)(Bp0 + k0 + 16) : make_float4(0.f, 0.f, 0.f, 0.f);
            fb1 = bv1 ? *(const float4*)(Bp1 + k0 + 16) : make_float4(0.f, 0.f, 0.f, 0.f);
        }

        const float* Ab = As[cur];
        const float* Bb = Bs[cur];
#pragma unroll
        for (int ks = 0; ks < 2; ks++) {
            int kidx = ks * 8 + (lane & 3);
            unsigned af[4][4], bf[4][2];
            int arow = wm * 64 + (lane >> 2);
#pragma unroll
            for (int mf = 0; mf < 4; mf++) {
                const float* p = Ab + (arow + mf * 16) * GP + kidx;
                af[mf][0] = fbits(p[0]);
                af[mf][1] = fbits(p[8 * GP]);
                af[mf][2] = fbits(p[4]);
                af[mf][3] = fbits(p[8 * GP + 4]);
            }
            int brow = wn * 32 + (lane >> 2);
#pragma unroll
            for (int nf = 0; nf < 4; nf++) {
                const float* p = Bb + (brow + nf * 8) * GP + kidx;
                bf[nf][0] = fbits(p[0]);
                bf[nf][1] = fbits(p[4]);
            }
#pragma unroll
            for (int mf = 0; mf < 4; mf++)
#pragma unroll
                for (int nf = 0; nf < 4; nf++)
                    mma_tf32(acc[mf][nf], af[mf], bf[nf]);
        }

        if (more) {
            int nxt = cur ^ 1;
            *(float4*)&As[nxt][lr * GP + lc] = make_float4(tf32r(fa0.x), tf32r(fa0.y), tf32r(fa0.z), tf32r(fa0.w));
            *(float4*)&As[nxt][(lr + 64) * GP + lc] = make_float4(tf32r(fa1.x), tf32r(fa1.y), tf32r(fa1.z), tf32r(fa1.w));
            *(float4*)&Bs[nxt][lr * GP + lc] = make_float4(tf32r(fb0.x), tf32r(fb0.y), tf32r(fb0.z), tf32r(fb0.w));
            *(float4*)&Bs[nxt][(lr + 64) * GP + lc] = make_float4(tf32r(fb1.x), tf32r(fb1.y), tf32r(fb1.z), tf32r(fb1.w));
        }
        __syncthreads();
        cur ^= 1;
    }

#pragma unroll
    for (int mf = 0; mf < 4; mf++) {
        int row0 = m0 + wm * 64 + mf * 16 + (lane >> 2);
#pragma unroll
        for (int nf = 0; nf < 4; nf++) {
            int col = n0 + wn * 32 + nf * 8 + 2 * (lane & 3);
            if (col < N) {
                float b0 = bias[col], b1 = bias[col + 1];
                float2 v0 = make_float2(acc[mf][nf][0] + b0, acc[mf][nf][1] + b1);
                float2 v1 = make_float2(acc[mf][nf][2] + b0, acc[mf][nf][3] + b1);
                *(float2*)&Cm[(size_t)row0 * N + col] = v0;
                *(float2*)&Cm[(size_t)(row0 + 8) * N + col] = v1;
            }
        }
    }
}

// ---------------- RMSNorm (row-wise) ----------------
__global__ void __launch_bounds__(256) rmsnorm_kernel(
    const float* __restrict__ src, int srcStride,
    float* __restrict__ dst, int dstStride,
    const float* __restrict__ w, int cols)
{
    int row = blockIdx.x;
    const float* s = src + (size_t)row * srcStride;
    float* d = dst + (size_t)row * dstStride;
    float sum = 0.f;
    for (int i = threadIdx.x; i < cols; i += 256) { float v = s[i]; sum += v * v; }
    __shared__ float red[256];
    red[threadIdx.x] = sum;
    __syncthreads();
    for (int o = 128; o > 0; o >>= 1) {
        if (threadIdx.x < o) red[threadIdx.x] += red[threadIdx.x + o];
        __syncthreads();
    }
    float inv = rsqrtf(red[0] / (float)cols + EPSF);
    for (int i = threadIdx.x; i < cols; i += 256) d[i] = s[i] * inv * w[i];
}

// ---------------- RoPE ----------------
__global__ void rope_q_kernel(const float* __restrict__ freqs) {
    int idx = blockIdx.x * blockDim.x + threadIdx.x;
    if (idx >= TT * HH * 32) return;
    int i = idx & 31;
    int h = (idx >> 5) & 15;
    int t = idx >> 9;
    float f = freqs[t * 32 + i];
    float c = cosf(f), s = sinf(f);
    float* p = g_q + (size_t)t * (HH * QKD) + h * QKD + DN + 2 * i;
    float x0 = p[0], x1 = p[1];
    p[0] = x0 * c - x1 * s;
    p[1] = x0 * s + x1 * c;
}

__global__ void rope_k_kernel(const float* __restrict__ freqs) {
    int idx = blockIdx.x * blockDim.x + threadIdx.x;
    if (idx >= TT * 32) return;
    int i = idx & 31;
    int t = idx >> 5;
    float f = freqs[t * 32 + i];
    float c = cosf(f), s = sinf(f);
    float* p = g_kvpe + (size_t)t * (RKV + DR) + RKV + 2 * i;
    float x0 = p[0], x1 = p[1];
    p[0] = x0 * c - x1 * s;
    p[1] = x0 * s + x1 * c;
}

// ---------------- Flash attention with tensor cores (causal, online softmax) ----------------
// Block = (head, 64-row q tile). 256 threads (8 warps, 4x2 grid).
// S tile 64x64 (warp tile 16x32), O tile 64x128 (warp tile 16x64). All mma tf32.
#define QP2 196
#define VP2 136
#define PP2 68
#define ATTN_FLOATS (64 * QP2 * 2 + 64 * VP2 + 64 * PP2 + 3 * 64)
#define ATTN_SMEM (ATTN_FLOATS * 4)

__global__ void __launch_bounds__(256, 1) attn_tc(
    const float* __restrict__ q, const float* __restrict__ kvb,
    const float* __restrict__ kvpe, float* __restrict__ y)
{
    extern __shared__ float sm[];
    float* Qs = sm;                    // 64 x 196 (tf32 of q*scale)
    float* Ks = Qs + 64 * QP2;         // 64 x 196
    float* Vs = Ks + 64 * QP2;         // 64 x 136 (row = token, col = dim)
    float* Ps = Vs + 64 * VP2;         // 64 x 68
    float* m_s = Ps + 64 * PP2;
    float* l_s = m_s + 64;
    float* al_s = l_s + 64;

    int h = blockIdx.y;
    int qt = gridDim.x - 1 - blockIdx.x;   // heavy tiles first
    int tid = threadIdx.x, lane = tid & 31, warp = tid >> 5;
    int wm = warp >> 1, wn = warp & 1;     // 4 x 2 warp grid

    for (int i = tid * 4; i < 64 * QKD; i += 1024) {
        int r = i / QKD, d = i - r * QKD;
        float4 v = *(const float4*)(q + (size_t)(qt * 64 + r) * (HH * QKD) + h * QKD + d);
        *(float4*)&Qs[r * QP2 + d] = make_float4(
            tf32r(v.x * SCALEF), tf32r(v.y * SCALEF), tf32r(v.z * SCALEF), tf32r(v.w * SCALEF));
    }
    if (tid < 64) { m_s[tid] = -1e30f; l_s[tid] = 0.f; }

    float oacc[8][4];
#pragma unroll
    for (int i = 0; i < 8; i++)
#pragma unroll
        for (int j = 0; j < 4; j++) oacc[i][j] = 0.f;

    __syncthreads();

    for (int kt = 0; kt <= qt; kt++) {
        // load K (128 nope from kvb + 64 pe from kvpe) and V, tf32-rounded
        for (int i = tid * 4; i < 64 * QKD; i += 1024) {
            int r = i / QKD, d = i - r * QKD;
            int t = kt * 64 + r;
            float4 v = (d < DN)
                ? *(const float4*)(kvb + (size_t)t * (HH * 256) + h * 256 + d)
                : *(const float4*)(kvpe + (size_t)t * (RKV + DR) + RKV + (d - DN));
            *(float4*)&Ks[r * QP2 + d] = make_float4(tf32r(v.x), tf32r(v.y), tf32r(v.z), tf32r(v.w));
        }
        for (int i = tid * 4; i < 64 * DV; i += 1024) {
            int r = i >> 7, d = i & 127;
            float4 v = *(const float4*)(kvb + (size_t)(kt * 64 + r) * (HH * 256) + h * 256 + DN + d);
            *(float4*)&Vs[r * VP2 + d] = make_float4(tf32r(v.x), tf32r(v.y), tf32r(v.z), tf32r(v.w));
        }
        __syncthreads();

        // ---- S = Q K^T (warp tile 16x32) ----
        float sacc[4][4];
#pragma unroll
        for (int i = 0; i < 4; i++)
#pragma unroll
            for (int j = 0; j < 4; j++) sacc[i][j] = 0.f;

        {
            const float* Abase = Qs + (wm * 16 + (lane >> 2)) * QP2 + (lane & 3);
#pragma unroll 4
            for (int k0 = 0; k0 < QKD; k0 += 8) {
                unsigned a[4];
                const float* p = Abase + k0;
                a[0] = fbits(p[0]);
                a[1] = fbits(p[8 * QP2]);
                a[2] = fbits(p[4]);
                a[3] = fbits(p[8 * QP2 + 4]);
#pragma unroll
                for (int nf = 0; nf < 4; nf++) {
                    const float* pb = Ks + (wn * 32 + nf * 8 + (lane >> 2)) * QP2 + k0 + (lane & 3);
                    unsigned b[2] = { fbits(pb[0]), fbits(pb[4]) };
                    mma_tf32(sacc[nf], a, b);
                }
            }
        }
#pragma unroll
        for (int nf = 0; nf < 4; nf++) {
            int r = wm * 16 + (lane >> 2);
            int c = wn * 32 + nf * 8 + 2 * (lane & 3);
            Ps[r * PP2 + c] = sacc[nf][0];
            Ps[r * PP2 + c + 1] = sacc[nf][1];
            Ps[(r + 8) * PP2 + c] = sacc[nf][2];
            Ps[(r + 8) * PP2 + c + 1] = sacc[nf][3];
        }
        __syncthreads();

        // ---- online softmax: 4 threads per row, 16 cols each ----
        {
            int row = tid >> 2, sub = tid & 3;
            float* pr = Ps + row * PP2 + sub * 16;
            bool diag = (kt == qt);
            float v[16];
#pragma unroll
            for (int j = 0; j < 16; j++) {
                float x = pr[j];
                if (diag && (sub * 16 + j) > row) x = -1e30f;
                v[j] = x;
            }
            float mx = v[0];
#pragma unroll
            for (int j = 1; j < 16; j++) mx = fmaxf(mx, v[j]);
            mx = fmaxf(mx, __shfl_xor_sync(0xffffffffu, mx, 1));
            mx = fmaxf(mx, __shfl_xor_sync(0xffffffffu, mx, 2));
            float mo = m_s[row];
            float mn = fmaxf(mo, mx);
            float sum = 0.f;
#pragma unroll
            for (int j = 0; j < 16; j++) {
                float p = __expf(v[j] - mn);
                sum += p;
                pr[j] = tf32r(p);
            }
            sum += __shfl_xor_sync(0xffffffffu, sum, 1);
            sum += __shfl_xor_sync(0xffffffffu, sum, 2);
            if (sub == 0) {
                float al = __expf(mo - mn);
                al_s[row] = al;
                l_s[row] = l_s[row] * al + sum;
                m_s[row] = mn;
            }
        }
        __syncthreads();

        // ---- O = O*alpha + P V (warp tile 16x64) ----
        {
            int r0 = wm * 16 + (lane >> 2);
            float al0 = al_s[r0], al1 = al_s[r0 + 8];
#pragma unroll
            for (int nf = 0; nf < 8; nf++) {
                oacc[nf][0] *= al0; oacc[nf][1] *= al0;
                oacc[nf][2] *= al1; oacc[nf][3] *= al1;
            }
            const float* Abase = Ps + r0 * PP2 + (lane & 3);
#pragma unroll
            for (int k0 = 0; k0 < 64; k0 += 8) {
                unsigned a[4];
                const float* p = Abase + k0;
                a[0] = fbits(p[0]);
                a[1] = fbits(p[8 * PP2]);
                a[2] = fbits(p[4]);
                a[3] = fbits(p[8 * PP2 + 4]);
#pragma unroll
                for (int nf = 0; nf < 8; nf++) {
                    const float* pb = Vs + (k0 + (lane & 3)) * VP2 + wn * 64 + nf * 8 + (lane >> 2);
                    unsigned b[2] = { fbits(pb[0]), fbits(pb[4 * VP2]) };
                    mma_tf32(oacc[nf], a, b);
                }
            }
        }
        __syncthreads();
    }

    // epilogue: divide by l, write y
    {
        int r0 = wm * 16 + (lane >> 2);
        float inv0 = 1.f / l_s[r0], inv1 = 1.f / l_s[r0 + 8];
        int t0 = qt * 64 + r0;
#pragma unroll
        for (int nf = 0; nf < 8; nf++) {
            int c = wn * 64 + nf * 8 + 2 * (lane & 3);
            float* y0 = y + (size_t)t0 * CC + h * DV + c;
            float* y1 = y + (size_t)(t0 + 8) * CC + h * DV + c;
            y0[0] = oacc[nf][0] * inv0;
            y0[1] = oacc[nf][1] * inv0;
            y1[0] = oacc[nf][2] * inv1;
            y1[1] = oacc[nf][3] * inv1;
        }
    }
}

// ---------------- launch ----------------
extern "C" void kernel_launch(void* const* d_in, const int* in_sizes, int n_in,
                              void* d_out, int out_size) {
    const float* x        = (const float*)d_in[0];
    const float* freqs    = (const float*)d_in[1];
    const float* wq_a     = (const float*)d_in[2];
    const float* bq_a     = (const float*)d_in[3];
    const float* q_norm_w = (const float*)d_in[4];
    const float* wq_b     = (const float*)d_in[5];
    const float* bq_b     = (const float*)d_in[6];
    const float* wkv_a    = (const float*)d_in[7];
    const float* bkv_a    = (const float*)d_in[8];
    const float* kv_norm_w= (const float*)d_in[9];
    const float* wkv_b    = (const float*)d_in[10];
    const float* bkv_b    = (const float*)d_in[11];
    const float* wo       = (const float*)d_in[12];
    const float* bo       = (const float*)d_in[13];
    float* out = (float*)d_out;

    float *qlat, *qbuf, *kvpe, *kvlat, *kvb, *ybuf;
    cudaGetSymbolAddress((void**)&qlat,  g_qlat);
    cudaGetSymbolAddress((void**)&qbuf,  g_q);
    cudaGetSymbolAddress((void**)&kvpe,  g_kvpe);
    cudaGetSymbolAddress((void**)&kvlat, g_kvlat);
    cudaGetSymbolAddress((void**)&kvb,   g_kvb);
    cudaGetSymbolAddress((void**)&ybuf,  g_y);

    cudaFuncSetAttribute(attn_tc, cudaFuncAttributeMaxDynamicSharedMemorySize, ATTN_SMEM);

    // Q path
    gemm_tc<<<dim3(RQ / 128, TT / 128), 256>>>(x, wq_a, bq_a, qlat, TT, RQ, CC);
    rmsnorm_kernel<<<TT, 256>>>(qlat, RQ, qlat, RQ, q_norm_w, RQ);
    gemm_tc<<<dim3((HH * QKD) / 128, TT / 128), 256>>>(qlat, wq_b, bq_b, qbuf, TT, HH * QKD, RQ);
    rope_q_kernel<<<(TT * HH * 32 + 255) / 256, 256>>>(freqs);

    // KV path
    gemm_tc<<<dim3((RKV + DR + 127) / 128, TT / 128), 256>>>(x, wkv_a, bkv_a, kvpe, TT, RKV + DR, CC);
    rope_k_kernel<<<(TT * 32 + 255) / 256, 256>>>(freqs);
    rmsnorm_kernel<<<TT, 256>>>(kvpe, RKV + DR, kvlat, RKV, kv_norm_w, RKV);
    gemm_tc<<<dim3((HH * 256) / 128, TT / 128), 256>>>(kvlat, wkv_b, bkv_b, kvb, TT, HH * 256, RKV);

    // Attention
    attn_tc<<<dim3(TT / 64, HH), 256, ATTN_SMEM>>>(qbuf, kvb, kvpe, ybuf);

    // Output projection
    gemm_tc<<<dim3(CC / 128, TT / 128), 256>>>(ybuf, wo, bo, out, TT, CC, CC);
}